// round 15
// baseline (speedup 1.0000x reference)
#include <cuda_runtime.h>
#include <cstdint>

// Problem shape (fixed)
#define BATCH 1024
#define NBLK  1024
#define DIN   64
#define DOUT  64
#define THREADS 256

#define ROWS_PER_CTA 512
#define ROWS_PER_IT  32
#define NUM_IT       (ROWS_PER_CTA / ROWS_PER_IT)   // 16

// Dynamic smem (float words), stride 68 (conflict-free LDS patterns):
//   xb[2] : double-buffered x tile [32][68] (raw, then rounded to tf32 in place)
//   wh    : [64][68] tf32-hi of W[n]
//   wl    : [64][68] residual W - wh (raw; MMA truncation handles it)
#define S68       68
#define XB_WORDS  (ROWS_PER_IT * S68)       // 2176
#define WH_OFF    (2 * XB_WORDS)            // 4352
#define WL_OFF    (WH_OFF + DOUT * S68)     // 8704
#define SMEM_WORDS (WL_OFF + DOUT * S68)    // 13056
#define SMEM_BYTES (SMEM_WORDS * 4)         // 52224 B

static __device__ __forceinline__ float tf32_rna(float v) {
    uint32_t u;
    asm("cvt.rna.tf32.f32 %0, %1;" : "=r"(u) : "f"(v));
    return __uint_as_float(u);
}

static __device__ __forceinline__ void mma_tf32(float4& d,
                                                uint32_t a0, uint32_t a1,
                                                uint32_t a2, uint32_t a3,
                                                uint32_t b0, uint32_t b1) {
    asm volatile(
        "mma.sync.aligned.m16n8k8.row.col.f32.tf32.tf32.f32 "
        "{%0,%1,%2,%3}, {%4,%5,%6,%7}, {%8,%9}, {%0,%1,%2,%3};"
        : "+f"(d.x), "+f"(d.y), "+f"(d.z), "+f"(d.w)
        : "r"(a0), "r"(a1), "r"(a2), "r"(a3), "r"(b0), "r"(b1));
}

static __device__ __forceinline__ void cp_async16(uint32_t smem_dst, const void* gptr) {
    asm volatile("cp.async.ca.shared.global [%0], [%1], 16;"
                 :: "r"(smem_dst), "l"(gptr) : "memory");
}
static __device__ __forceinline__ void cp_commit() {
    asm volatile("cp.async.commit_group;" ::: "memory");
}
template <int N>
static __device__ __forceinline__ void cp_wait() {
    asm volatile("cp.async.wait_group %0;" :: "n"(N) : "memory");
}
static __device__ __forceinline__ uint32_t smem_u32(const void* p) {
    uint32_t a;
    asm("{ .reg .u64 t; cvta.to.shared.u64 t, %1; cvt.u32.u64 %0, t; }"
        : "=r"(a) : "l"(p));
    return a;
}

__global__ __launch_bounds__(THREADS, 2)
void block_linear_mma(const float* __restrict__ x,
                      const float* __restrict__ W,
                      const float* __restrict__ bias,
                      float* __restrict__ out) {
    extern __shared__ float sm[];
    const uint32_t sb = smem_u32(sm);

    const int n   = blockIdx.y;
    const int b0  = blockIdx.x * ROWS_PER_CTA;
    const int tid = threadIdx.x;
    const int wid  = tid >> 5;
    const int lane = tid & 31;

    // warp grid: 4 n-warps x 2 m-warps
    const int nw = wid & 3;           // cols nw*16 .. nw*16+15 (2 n-tiles)
    const int mw = wid >> 2;          // rows mw*16 .. mw*16+15 within iteration
    const int cb = nw * 16;
    const int m0 = mw * 16;
    const int gr = lane >> 2;
    const int c  = lane & 3;

    // ---- issue x tile 0 via cp.async FIRST (overlaps with W staging below)
    {
        #pragma unroll
        for (int it2 = 0; it2 < 2; it2++) {
            int idx = tid + it2 * THREADS;     // 0..511 float4 slots
            int m   = idx >> 4;
            int c4  = idx & 15;
            const float* src = x + ((size_t)(b0 + m) * NBLK + n) * DIN + c4 * 4;
            cp_async16(sb + (m * S68 + c4 * 4) * 4, src);
        }
        cp_commit();
    }

    // ---- stage W[n]: wh = rna(W), wl = W - wh (exact split; wl left raw)
    {
        #pragma unroll
        for (int it2 = 0; it2 < 2; it2++) {
            int ch = tid + it2 * THREADS;      // 0..511 : (o, s) chunks of 8 k
            int o  = ch >> 3;
            int s  = ch & 7;
            const float* wrow = W + (size_t)n * (DOUT * DIN) + o * DIN + s * 8;
            float4 va = *(const float4*)(wrow);
            float4 vb = *(const float4*)(wrow + 4);
            float4 ha, hb, la, lb;
            ha.x = tf32_rna(va.x); la.x = va.x - ha.x;
            ha.y = tf32_rna(va.y); la.y = va.y - ha.y;
            ha.z = tf32_rna(va.z); la.z = va.z - ha.z;
            ha.w = tf32_rna(va.w); la.w = va.w - ha.w;
            hb.x = tf32_rna(vb.x); lb.x = vb.x - hb.x;
            hb.y = tf32_rna(vb.y); lb.y = vb.y - hb.y;
            hb.z = tf32_rna(vb.z); lb.z = vb.z - hb.z;
            hb.w = tf32_rna(vb.w); lb.w = vb.w - hb.w;
            float* ph = &sm[WH_OFF + o * S68 + s * 8];
            float* pl = &sm[WL_OFF + o * S68 + s * 8];
            *(float4*)(ph)     = ha;  *(float4*)(ph + 4) = hb;
            *(float4*)(pl)     = la;  *(float4*)(pl + 4) = lb;
        }
    }
    __syncthreads();

    // ---- this warp's B fragments (hi+lo) into registers, held all kernel
    uint2 bh[2][8], bl[2][8];
    #pragma unroll
    for (int j = 0; j < 2; j++) {
        const int o = cb + 8 * j + gr;
        #pragma unroll
        for (int s = 0; s < 8; s++) {
            bh[j][s].x = __float_as_uint(sm[WH_OFF + o * S68 + 8 * s + c]);
            bh[j][s].y = __float_as_uint(sm[WH_OFF + o * S68 + 8 * s + c + 4]);
            bl[j][s].x = __float_as_uint(sm[WL_OFF + o * S68 + 8 * s + c]);
            bl[j][s].y = __float_as_uint(sm[WL_OFF + o * S68 + 8 * s + c + 4]);
        }
    }

    // bias for this lane's output columns (cols cb+8j+2c, +1)
    const float2 bj0 = *(const float2*)(bias + (size_t)n * DOUT + cb + 2 * c);
    const float2 bj1 = *(const float2*)(bias + (size_t)n * DOUT + cb + 8 + 2 * c);

    // ---- persistent batch loop, double-buffered x tiles
    for (int it = 0; it < NUM_IT; it++) {
        const int cur = it & 1;

        if (it + 1 < NUM_IT) {
            const int rb = b0 + (it + 1) * ROWS_PER_IT;
            const uint32_t dstb = sb + ((cur ^ 1) * XB_WORDS) * 4;
            #pragma unroll
            for (int it2 = 0; it2 < 2; it2++) {
                int idx = tid + it2 * THREADS;
                int m   = idx >> 4;
                int c4  = idx & 15;
                const float* src = x + ((size_t)(rb + m) * NBLK + n) * DIN + c4 * 4;
                cp_async16(dstb + (m * S68 + c4 * 4) * 4, src);
            }
            cp_commit();
            cp_wait<1>();
        } else {
            cp_wait<0>();
        }
        __syncthreads();

        // ---- round current x tile to tf32 in place (once, amortized)
        {
            #pragma unroll
            for (int it2 = 0; it2 < 2; it2++) {
                int idx = tid + it2 * THREADS;   // 0..511 float4 slots
                int m   = idx >> 4;
                int c4  = idx & 15;
                float4* p = (float4*)&sm[cur * XB_WORDS + m * S68 + c4 * 4];
                float4 v = *p;
                v.x = tf32_rna(v.x); v.y = tf32_rna(v.y);
                v.z = tf32_rna(v.z); v.w = tf32_rna(v.w);
                *p = v;
            }
        }
        __syncthreads();

        float4 acc0 = make_float4(0.f, 0.f, 0.f, 0.f);
        float4 acc1 = make_float4(0.f, 0.f, 0.f, 0.f);

        const float* xa0 = &sm[cur * XB_WORDS + (m0 + gr) * S68 + c];
        const float* xa1 = xa0 + 8 * S68;

        #pragma unroll
        for (int s = 0; s < 8; s++) {
            // A fragment already tf32-rounded: pure LDS -> MMA
            uint32_t a0 = __float_as_uint(xa0[8 * s]);
            uint32_t a1 = __float_as_uint(xa1[8 * s]);
            uint32_t a2 = __float_as_uint(xa0[8 * s + 4]);
            uint32_t a3 = __float_as_uint(xa1[8 * s + 4]);

            mma_tf32(acc0, a0, a1, a2, a3, bh[0][s].x, bh[0][s].y);
            mma_tf32(acc1, a0, a1, a2, a3, bh[1][s].x, bh[1][s].y);
            mma_tf32(acc0, a0, a1, a2, a3, bl[0][s].x, bl[0][s].y);
            mma_tf32(acc1, a0, a1, a2, a3, bl[1][s].x, bl[1][s].y);
        }

        // epilogue for this 32-row tile
        {
            const int r0 = b0 + it * ROWS_PER_IT + m0 + gr;
            float* orow0 = out + ((size_t)r0 * NBLK + n) * DOUT;
            float* orow1 = out + ((size_t)(r0 + 8) * NBLK + n) * DOUT;
            *(float2*)(orow0 + cb + 2 * c)     = make_float2(acc0.x + bj0.x, acc0.y + bj0.y);
            *(float2*)(orow1 + cb + 2 * c)     = make_float2(acc0.z + bj0.x, acc0.w + bj0.y);
            *(float2*)(orow0 + cb + 8 + 2 * c) = make_float2(acc1.x + bj1.x, acc1.y + bj1.y);
            *(float2*)(orow1 + cb + 8 + 2 * c) = make_float2(acc1.z + bj1.x, acc1.w + bj1.y);
        }
        __syncthreads();
    }
}

extern "C" void kernel_launch(void* const* d_in, const int* in_sizes, int n_in,
                              void* d_out, int out_size) {
    const float* x = (const float*)d_in[0];
    const float* W = (const float*)d_in[1];
    const float* b = (const float*)d_in[2];
    float* out = (float*)d_out;

    cudaFuncSetAttribute(block_linear_mma,
                         cudaFuncAttributeMaxDynamicSharedMemorySize, SMEM_BYTES);

    dim3 grid(BATCH / ROWS_PER_CTA, NBLK);
    block_linear_mma<<<grid, THREADS, SMEM_BYTES>>>(x, W, b, out);
}

// round 16
// speedup vs baseline: 1.0602x; 1.0602x over previous
#include <cuda_runtime.h>
#include <cstdint>

// Problem shape (fixed)
#define BATCH 1024
#define NBLK  1024
#define DIN   64
#define DOUT  64
#define THREADS 256

#define ROWS_PER_CTA 512
#define ROWS_PER_IT  64
#define NUM_IT       (ROWS_PER_CTA / ROWS_PER_IT)   // 8

// Dynamic smem (float words), stride 68 (conflict-free LDS patterns):
//   xb[2] : double-buffered raw x tile [64][68]
//   wh    : [64][68] tf32-rounded W[n]
#define S68       68
#define XB_WORDS  (ROWS_PER_IT * S68)       // 4352
#define WH_OFF    (2 * XB_WORDS)            // 8704
#define SMEM_WORDS (WH_OFF + DOUT * S68)    // 13056
#define SMEM_BYTES (SMEM_WORDS * 4)         // 52224 B -> 3 CTAs/SM (157KB)

static __device__ __forceinline__ float tf32_rna(float v) {
    uint32_t u;
    asm("cvt.rna.tf32.f32 %0, %1;" : "=r"(u) : "f"(v));
    return __uint_as_float(u);
}

static __device__ __forceinline__ void mma_tf32(float4& d,
                                                uint32_t a0, uint32_t a1,
                                                uint32_t a2, uint32_t a3,
                                                uint32_t b0, uint32_t b1) {
    asm volatile(
        "mma.sync.aligned.m16n8k8.row.col.f32.tf32.tf32.f32 "
        "{%0,%1,%2,%3}, {%4,%5,%6,%7}, {%8,%9}, {%0,%1,%2,%3};"
        : "+f"(d.x), "+f"(d.y), "+f"(d.z), "+f"(d.w)
        : "r"(a0), "r"(a1), "r"(a2), "r"(a3), "r"(b0), "r"(b1));
}

static __device__ __forceinline__ void cp_async16(uint32_t smem_dst, const void* gptr) {
    asm volatile("cp.async.ca.shared.global [%0], [%1], 16;"
                 :: "r"(smem_dst), "l"(gptr) : "memory");
}
static __device__ __forceinline__ void cp_commit() {
    asm volatile("cp.async.commit_group;" ::: "memory");
}
template <int N>
static __device__ __forceinline__ void cp_wait() {
    asm volatile("cp.async.wait_group %0;" :: "n"(N) : "memory");
}
static __device__ __forceinline__ uint32_t smem_u32(const void* p) {
    uint32_t a;
    asm("{ .reg .u64 t; cvta.to.shared.u64 t, %1; cvt.u32.u64 %0, t; }"
        : "=r"(a) : "l"(p));
    return a;
}

__global__ __launch_bounds__(THREADS, 3)
void block_linear_mma(const float* __restrict__ x,
                      const float* __restrict__ W,
                      const float* __restrict__ bias,
                      float* __restrict__ out) {
    extern __shared__ float sm[];
    const uint32_t sb = smem_u32(sm);

    const int n   = blockIdx.y;
    const int b0  = blockIdx.x * ROWS_PER_CTA;
    const int tid = threadIdx.x;
    const int wid  = tid >> 5;
    const int lane = tid & 31;

    // warp grid: 4 n-warps x 2 m-warps; each m-warp covers 32 rows (2 m16 tiles)
    const int nw = wid & 3;           // cols nw*16 .. nw*16+15 (2 n-tiles)
    const int mw = wid >> 2;          // rows mw*32 .. mw*32+31
    const int cb = nw * 16;
    const int m0 = mw * 32;
    const int gr = lane >> 2;
    const int c  = lane & 3;

    // ---- issue x tile 0 via cp.async FIRST (overlaps with W staging below)
    {
        #pragma unroll
        for (int it2 = 0; it2 < 4; it2++) {
            int idx = tid + it2 * THREADS;     // 0..1023 float4 slots
            int m   = idx >> 4;
            int c4  = idx & 15;
            const float* src = x + ((size_t)(b0 + m) * NBLK + n) * DIN + c4 * 4;
            cp_async16(sb + (m * S68 + c4 * 4) * 4, src);
        }
        cp_commit();
    }

    // ---- stage W[n] rounded once to tf32 ([o][k] layout, stride 68)
    {
        #pragma unroll
        for (int it2 = 0; it2 < 2; it2++) {
            int ch = tid + it2 * THREADS;      // 0..511 : (o, s) chunks of 8 k
            int o  = ch >> 3;
            int s  = ch & 7;
            const float* wrow = W + (size_t)n * (DOUT * DIN) + o * DIN + s * 8;
            float4 va = *(const float4*)(wrow);
            float4 vb = *(const float4*)(wrow + 4);
            float4 ha, hb;
            ha.x = tf32_rna(va.x); ha.y = tf32_rna(va.y);
            ha.z = tf32_rna(va.z); ha.w = tf32_rna(va.w);
            hb.x = tf32_rna(vb.x); hb.y = tf32_rna(vb.y);
            hb.z = tf32_rna(vb.z); hb.w = tf32_rna(vb.w);
            float* ph = &sm[WH_OFF + o * S68 + s * 8];
            *(float4*)(ph)     = ha;
            *(float4*)(ph + 4) = hb;
        }
    }
    __syncthreads();

    // ---- this warp's B fragments into registers (held for whole kernel)
    uint2 bh[2][8];
    #pragma unroll
    for (int j = 0; j < 2; j++) {
        const int o = cb + 8 * j + gr;
        #pragma unroll
        for (int s = 0; s < 8; s++) {
            bh[j][s].x = __float_as_uint(sm[WH_OFF + o * S68 + 8 * s + c]);
            bh[j][s].y = __float_as_uint(sm[WH_OFF + o * S68 + 8 * s + c + 4]);
        }
    }

    // bias for this lane's output columns (cols cb+8j+2c, +1)
    const float2 bj0 = *(const float2*)(bias + (size_t)n * DOUT + cb + 2 * c);
    const float2 bj1 = *(const float2*)(bias + (size_t)n * DOUT + cb + 8 + 2 * c);

    // ---- persistent batch loop, double-buffered x tiles
    for (int it = 0; it < NUM_IT; it++) {
        const int cur = it & 1;

        if (it + 1 < NUM_IT) {
            const int rb = b0 + (it + 1) * ROWS_PER_IT;
            const uint32_t dstb = sb + ((cur ^ 1) * XB_WORDS) * 4;
            #pragma unroll
            for (int it2 = 0; it2 < 4; it2++) {
                int idx = tid + it2 * THREADS;
                int m   = idx >> 4;
                int c4  = idx & 15;
                const float* src = x + ((size_t)(rb + m) * NBLK + n) * DIN + c4 * 4;
                cp_async16(dstb + (m * S68 + c4 * 4) * 4, src);
            }
            cp_commit();
            cp_wait<1>();
        } else {
            cp_wait<0>();
        }
        __syncthreads();

        // 4 independent accumulator chains: [m-tile][n-tile]
        float4 acc[2][2];
        #pragma unroll
        for (int mt = 0; mt < 2; mt++)
            #pragma unroll
            for (int j = 0; j < 2; j++)
                acc[mt][j] = make_float4(0.f, 0.f, 0.f, 0.f);

        const float* xr0 = &sm[cur * XB_WORDS + (m0 + gr) * S68 + c];

        #pragma unroll
        for (int s = 0; s < 8; s++) {
            #pragma unroll
            for (int mt = 0; mt < 2; mt++) {
                const float* xa0 = xr0 + (mt * 16) * S68;
                const float* xa1 = xa0 + 8 * S68;
                // exact 2-term split: xh = rna(x), xl = x - xh (raw; MMA truncates)
                float ra0 = xa0[8 * s],     ra1 = xa1[8 * s];
                float ra2 = xa0[8 * s + 4], ra3 = xa1[8 * s + 4];
                float h0 = tf32_rna(ra0), h1 = tf32_rna(ra1);
                float h2 = tf32_rna(ra2), h3 = tf32_rna(ra3);
                uint32_t ah0 = __float_as_uint(h0), ah1 = __float_as_uint(h1);
                uint32_t ah2 = __float_as_uint(h2), ah3 = __float_as_uint(h3);
                uint32_t al0 = __float_as_uint(ra0 - h0);
                uint32_t al1 = __float_as_uint(ra1 - h1);
                uint32_t al2 = __float_as_uint(ra2 - h2);
                uint32_t al3 = __float_as_uint(ra3 - h3);

                mma_tf32(acc[mt][0], ah0, ah1, ah2, ah3, bh[0][s].x, bh[0][s].y);
                mma_tf32(acc[mt][1], ah0, ah1, ah2, ah3, bh[1][s].x, bh[1][s].y);
                mma_tf32(acc[mt][0], al0, al1, al2, al3, bh[0][s].x, bh[0][s].y);
                mma_tf32(acc[mt][1], al0, al1, al2, al3, bh[1][s].x, bh[1][s].y);
            }
        }

        // epilogue for this 64-row tile
        #pragma unroll
        for (int mt = 0; mt < 2; mt++) {
            const int r0 = b0 + it * ROWS_PER_IT + m0 + mt * 16 + gr;
            float* orow0 = out + ((size_t)r0 * NBLK + n) * DOUT;
            float* orow1 = out + ((size_t)(r0 + 8) * NBLK + n) * DOUT;
            *(float2*)(orow0 + cb + 2 * c) =
                make_float2(acc[mt][0].x + bj0.x, acc[mt][0].y + bj0.y);
            *(float2*)(orow1 + cb + 2 * c) =
                make_float2(acc[mt][0].z + bj0.x, acc[mt][0].w + bj0.y);
            *(float2*)(orow0 + cb + 8 + 2 * c) =
                make_float2(acc[mt][1].x + bj1.x, acc[mt][1].y + bj1.y);
            *(float2*)(orow1 + cb + 8 + 2 * c) =
                make_float2(acc[mt][1].z + bj1.x, acc[mt][1].w + bj1.y);
        }
        __syncthreads();
    }
}

extern "C" void kernel_launch(void* const* d_in, const int* in_sizes, int n_in,
                              void* d_out, int out_size) {
    const float* x = (const float*)d_in[0];
    const float* W = (const float*)d_in[1];
    const float* b = (const float*)d_in[2];
    float* out = (float*)d_out;

    cudaFuncSetAttribute(block_linear_mma,
                         cudaFuncAttributeMaxDynamicSharedMemorySize, SMEM_BYTES);

    dim3 grid(BATCH / ROWS_PER_CTA, NBLK);
    block_linear_mma<<<grid, THREADS, SMEM_BYTES>>>(x, W, b, out);
}

// round 17
// speedup vs baseline: 1.1590x; 1.0932x over previous
#include <cuda_runtime.h>
#include <cstdint>

// Problem shape (fixed)
#define BATCH 1024
#define NBLK  1024
#define DIN   64
#define DOUT  64
#define THREADS 256

#define ROWS_PER_CTA 512
#define ROWS_PER_IT  64
#define NUM_IT       (ROWS_PER_CTA / ROWS_PER_IT)   // 8

// Dynamic smem (float words), stride 68 (conflict-free LDS patterns):
//   xb[2] : double-buffered raw x tile [64][68]
//   wh    : [64][68] tf32-rounded W[n]
#define S68       68
#define XB_WORDS  (ROWS_PER_IT * S68)       // 4352
#define WH_OFF    (2 * XB_WORDS)            // 8704
#define SMEM_WORDS (WH_OFF + DOUT * S68)    // 13056
#define SMEM_BYTES (SMEM_WORDS * 4)         // 52224 B -> 3 CTAs/SM (157KB)

static __device__ __forceinline__ float tf32_rna(float v) {
    uint32_t u;
    asm("cvt.rna.tf32.f32 %0, %1;" : "=r"(u) : "f"(v));
    return __uint_as_float(u);
}

static __device__ __forceinline__ void mma_tf32(float4& d,
                                                uint32_t a0, uint32_t a1,
                                                uint32_t a2, uint32_t a3,
                                                uint32_t b0, uint32_t b1) {
    asm volatile(
        "mma.sync.aligned.m16n8k8.row.col.f32.tf32.tf32.f32 "
        "{%0,%1,%2,%3}, {%4,%5,%6,%7}, {%8,%9}, {%0,%1,%2,%3};"
        : "+f"(d.x), "+f"(d.y), "+f"(d.z), "+f"(d.w)
        : "r"(a0), "r"(a1), "r"(a2), "r"(a3), "r"(b0), "r"(b1));
}

static __device__ __forceinline__ void cp_async16(uint32_t smem_dst, const void* gptr) {
    asm volatile("cp.async.ca.shared.global [%0], [%1], 16;"
                 :: "r"(smem_dst), "l"(gptr) : "memory");
}
static __device__ __forceinline__ void cp_commit() {
    asm volatile("cp.async.commit_group;" ::: "memory");
}
template <int N>
static __device__ __forceinline__ void cp_wait() {
    asm volatile("cp.async.wait_group %0;" :: "n"(N) : "memory");
}
static __device__ __forceinline__ uint32_t smem_u32(const void* p) {
    uint32_t a;
    asm("{ .reg .u64 t; cvta.to.shared.u64 t, %1; cvt.u32.u64 %0, t; }"
        : "=r"(a) : "l"(p));
    return a;
}

__global__ __launch_bounds__(THREADS, 3)
void block_linear_mma(const float* __restrict__ x,
                      const float* __restrict__ W,
                      const float* __restrict__ bias,
                      float* __restrict__ out) {
    extern __shared__ float sm[];
    const uint32_t sb = smem_u32(sm);

    const int n   = blockIdx.y;
    const int b0  = blockIdx.x * ROWS_PER_CTA;
    const int tid = threadIdx.x;
    const int wid  = tid >> 5;
    const int lane = tid & 31;

    // warp grid: 4 n-warps x 2 m-warps; each m-warp covers 32 rows (2 m16 tiles)
    const int nw = wid & 3;           // cols nw*16 .. nw*16+15 (2 n-tiles)
    const int mw = wid >> 2;          // rows mw*32 .. mw*32+31
    const int cb = nw * 16;
    const int m0 = mw * 32;
    const int gr = lane >> 2;
    const int c  = lane & 3;

    // ---- issue x tile 0 via cp.async FIRST (overlaps with W staging below)
    {
        #pragma unroll
        for (int it2 = 0; it2 < 4; it2++) {
            int idx = tid + it2 * THREADS;     // 0..1023 float4 slots
            int m   = idx >> 4;
            int c4  = idx & 15;
            const float* src = x + ((size_t)(b0 + m) * NBLK + n) * DIN + c4 * 4;
            cp_async16(sb + (m * S68 + c4 * 4) * 4, src);
        }
        cp_commit();
    }

    // ---- stage W[n] rounded once to tf32 ([o][k] layout, stride 68).
    // W keeps rna rounding (off the critical path; best error constant).
    {
        #pragma unroll
        for (int it2 = 0; it2 < 2; it2++) {
            int ch = tid + it2 * THREADS;      // 0..511 : (o, s) chunks of 8 k
            int o  = ch >> 3;
            int s  = ch & 7;
            const float* wrow = W + (size_t)n * (DOUT * DIN) + o * DIN + s * 8;
            float4 va = *(const float4*)(wrow);
            float4 vb = *(const float4*)(wrow + 4);
            float4 ha, hb;
            ha.x = tf32_rna(va.x); ha.y = tf32_rna(va.y);
            ha.z = tf32_rna(va.z); ha.w = tf32_rna(va.w);
            hb.x = tf32_rna(vb.x); hb.y = tf32_rna(vb.y);
            hb.z = tf32_rna(vb.z); hb.w = tf32_rna(vb.w);
            float* ph = &sm[WH_OFF + o * S68 + s * 8];
            *(float4*)(ph)     = ha;
            *(float4*)(ph + 4) = hb;
        }
    }
    __syncthreads();

    // ---- this warp's B fragments into registers (held for whole kernel)
    uint2 bh[2][8];
    #pragma unroll
    for (int j = 0; j < 2; j++) {
        const int o = cb + 8 * j + gr;
        #pragma unroll
        for (int s = 0; s < 8; s++) {
            bh[j][s].x = __float_as_uint(sm[WH_OFF + o * S68 + 8 * s + c]);
            bh[j][s].y = __float_as_uint(sm[WH_OFF + o * S68 + 8 * s + c + 4]);
        }
    }

    // bias for this lane's output columns (cols cb+8j+2c, +1)
    const float2 bj0 = *(const float2*)(bias + (size_t)n * DOUT + cb + 2 * c);
    const float2 bj1 = *(const float2*)(bias + (size_t)n * DOUT + cb + 8 + 2 * c);

    // ---- persistent batch loop, double-buffered x tiles
    for (int it = 0; it < NUM_IT; it++) {
        const int cur = it & 1;

        if (it + 1 < NUM_IT) {
            const int rb = b0 + (it + 1) * ROWS_PER_IT;
            const uint32_t dstb = sb + ((cur ^ 1) * XB_WORDS) * 4;
            #pragma unroll
            for (int it2 = 0; it2 < 4; it2++) {
                int idx = tid + it2 * THREADS;
                int m   = idx >> 4;
                int c4  = idx & 15;
                const float* src = x + ((size_t)(rb + m) * NBLK + n) * DIN + c4 * 4;
                cp_async16(dstb + (m * S68 + c4 * 4) * 4, src);
            }
            cp_commit();
            cp_wait<1>();
        } else {
            cp_wait<0>();
        }
        __syncthreads();

        // 4 independent accumulator chains: [m-tile][n-tile]
        float4 acc[2][2];
        #pragma unroll
        for (int mt = 0; mt < 2; mt++)
            #pragma unroll
            for (int j = 0; j < 2; j++)
                acc[mt][j] = make_float4(0.f, 0.f, 0.f, 0.f);

        const float* xr0 = &sm[cur * XB_WORDS + (m0 + gr) * S68 + c];

        #pragma unroll
        for (int s = 0; s < 8; s++) {
            #pragma unroll
            for (int mt = 0; mt < 2; mt++) {
                const float* xa0 = xr0 + (mt * 16) * S68;
                const float* xa1 = xa0 + 8 * S68;
                // Truncation split on the critical path: xh = x & ~0x1FFF
                // (LOP3 lat 4 instead of cvt.rna.tf32 lat ~20). xl = x - xh is
                // exact; MMA's own mantissa truncation of xl costs ~2^-23|x|.
                float ra0 = xa0[8 * s],     ra1 = xa1[8 * s];
                float ra2 = xa0[8 * s + 4], ra3 = xa1[8 * s + 4];
                uint32_t ah0 = __float_as_uint(ra0) & 0xFFFFE000u;
                uint32_t ah1 = __float_as_uint(ra1) & 0xFFFFE000u;
                uint32_t ah2 = __float_as_uint(ra2) & 0xFFFFE000u;
                uint32_t ah3 = __float_as_uint(ra3) & 0xFFFFE000u;
                uint32_t al0 = __float_as_uint(ra0 - __uint_as_float(ah0));
                uint32_t al1 = __float_as_uint(ra1 - __uint_as_float(ah1));
                uint32_t al2 = __float_as_uint(ra2 - __uint_as_float(ah2));
                uint32_t al3 = __float_as_uint(ra3 - __uint_as_float(ah3));

                mma_tf32(acc[mt][0], ah0, ah1, ah2, ah3, bh[0][s].x, bh[0][s].y);
                mma_tf32(acc[mt][1], ah0, ah1, ah2, ah3, bh[1][s].x, bh[1][s].y);
                mma_tf32(acc[mt][0], al0, al1, al2, al3, bh[0][s].x, bh[0][s].y);
                mma_tf32(acc[mt][1], al0, al1, al2, al3, bh[1][s].x, bh[1][s].y);
            }
        }

        // epilogue for this 64-row tile
        #pragma unroll
        for (int mt = 0; mt < 2; mt++) {
            const int r0 = b0 + it * ROWS_PER_IT + m0 + mt * 16 + gr;
            float* orow0 = out + ((size_t)r0 * NBLK + n) * DOUT;
            float* orow1 = out + ((size_t)(r0 + 8) * NBLK + n) * DOUT;
            *(float2*)(orow0 + cb + 2 * c) =
                make_float2(acc[mt][0].x + bj0.x, acc[mt][0].y + bj0.y);
            *(float2*)(orow1 + cb + 2 * c) =
                make_float2(acc[mt][0].z + bj0.x, acc[mt][0].w + bj0.y);
            *(float2*)(orow0 + cb + 8 + 2 * c) =
                make_float2(acc[mt][1].x + bj1.x, acc[mt][1].y + bj1.y);
            *(float2*)(orow1 + cb + 8 + 2 * c) =
                make_float2(acc[mt][1].z + bj1.x, acc[mt][1].w + bj1.y);
        }
        __syncthreads();
    }
}

extern "C" void kernel_launch(void* const* d_in, const int* in_sizes, int n_in,
                              void* d_out, int out_size) {
    const float* x = (const float*)d_in[0];
    const float* W = (const float*)d_in[1];
    const float* b = (const float*)d_in[2];
    float* out = (float*)d_out;

    cudaFuncSetAttribute(block_linear_mma,
                         cudaFuncAttributeMaxDynamicSharedMemorySize, SMEM_BYTES);

    dim3 grid(BATCH / ROWS_PER_CTA, NBLK);
    block_linear_mma<<<grid, THREADS, SMEM_BYTES>>>(x, W, b, out);
}